// round 17
// baseline (speedup 1.0000x reference)
#include <cuda_runtime.h>
#include <cuda_fp16.h>

#define B_  4
#define N_  8192
#define C_  64
#define M_  2048
#define NW_ 7
#define NQB2 16          // 2048 / 128
#define KST3 36
#define WST2 36
#define OST 36
#define SSBW (128*KST3*2)
#define SCALE_LOG2 0.18033688011112042f

__device__ unsigned g_Qh[B_*N_*32];
__device__ unsigned g_Kh[B_*N_*32];
__device__ unsigned g_Vh[B_*N_*32];
__device__ unsigned g_Oh[(long)B_*NW_*M_*32];
__device__ float g_D[B_*NW_*M_];

__device__ __forceinline__ float ex2(float x) {
    float y; asm("ex2.approx.f32 %0, %1;" : "=f"(y) : "f"(x)); return y;
}
__device__ __forceinline__ void mma16(float d[4], unsigned a0, unsigned a1, unsigned a2,
                                      unsigned a3, unsigned b0, unsigned b1) {
    asm volatile("mma.sync.aligned.m16n8k16.row.col.f32.f16.f16.f32 "
        "{%0,%1,%2,%3},{%4,%5,%6,%7},{%8,%9},{%0,%1,%2,%3};"
        : "+f"(d[0]), "+f"(d[1]), "+f"(d[2]), "+f"(d[3])
        : "r"(a0), "r"(a1), "r"(a2), "r"(a3), "r"(b0), "r"(b1));
}
#define PACK2(D, HI, LO) asm("cvt.rn.f16x2.f32 %0, %1, %2;" : "=r"(D) : "f"(HI), "f"(LO))
#define LDSM4(R0, R1, R2, R3, ADDR) \
    asm volatile("ldmatrix.sync.aligned.m8n8.x4.shared.b16 {%0,%1,%2,%3}, [%4];" \
        : "=r"(R0), "=r"(R1), "=r"(R2), "=r"(R3) : "r"(ADDR))
#define LDSM4T(R0, R1, R2, R3, ADDR) \
    asm volatile("ldmatrix.sync.aligned.m8n8.x4.trans.shared.b16 {%0,%1,%2,%3}, [%4];" \
        : "=r"(R0), "=r"(R1), "=r"(R2), "=r"(R3) : "r"(ADDR))
#define CPA16(DST, SRC) \
    asm volatile("cp.async.cg.shared.global [%0], [%1], 16;" :: "r"(DST), "l"(SRC))

// ====== Kernel 1: QKV — fp16 TC, 256 thr / 64 rows / 2 CTAs per SM ======
__global__ __launch_bounds__(256, 2) void qkv_kernel(const float* __restrict__ x,
                                                     const float* __restrict__ Wq,
                                                     const float* __restrict__ Wk,
                                                     const float* __restrict__ Wv) {
    extern __shared__ unsigned sm[];
    unsigned* smw  = sm;                 // Wt16[192][WST2]
    unsigned* sout = sm + 192*WST2;      // bounce [3][64][OST]
    const int tid = threadIdx.x;
    const int wid = tid >> 5, lane = tid & 31;
    const int g = lane >> 2, t4 = lane & 3;
    const int rw = wid >> 1;             // 0..3
    const int jh = (wid & 1) * 12;

    // hoisted x loads (overlap W staging)
    const long row0 = (long)blockIdx.x*64 + 16*rw;
    unsigned a[4][4];
    {
        const float* x0 = x + (row0 + g)*C_;
        const float* x1 = x0 + 8*C_;
        #pragma unroll
        for (int kc = 0; kc < 4; kc++) {
            int k0 = 16*kc + 2*t4;
            float2 l0 = *(const float2*)(x0 + k0);
            float2 h0 = *(const float2*)(x0 + k0 + 8);
            float2 l1 = *(const float2*)(x1 + k0);
            float2 h1 = *(const float2*)(x1 + k0 + 8);
            PACK2(a[kc][0], l0.y, l0.x);
            PACK2(a[kc][1], l1.y, l1.x);
            PACK2(a[kc][2], h0.y, h0.x);
            PACK2(a[kc][3], h1.y, h1.x);
        }
    }

    const float* Wm[3] = {Wq, Wk, Wv};
    for (int idx = tid; idx < 192*32; idx += 256) {
        int w = idx / 192, nn = idx % 192;
        const float* Wsrc = Wm[nn >> 6];
        float lo = Wsrc[(2*w    )*64 + (nn & 63)];
        float hi = Wsrc[(2*w + 1)*64 + (nn & 63)];
        unsigned pw; PACK2(pw, hi, lo);
        smw[nn*WST2 + w] = pw;
    }
    __syncthreads();

    float acc[12][4];
    #pragma unroll
    for (int j = 0; j < 12; j++)
        #pragma unroll
        for (int q = 0; q < 4; q++) acc[j][q] = 0.f;

    #pragma unroll
    for (int kc = 0; kc < 4; kc++) {
        #pragma unroll
        for (int j = 0; j < 12; j++) {
            unsigned b0 = smw[(8*(jh + j) + g)*WST2 + 8*kc + t4];
            unsigned b1 = smw[(8*(jh + j) + g)*WST2 + 8*kc + t4 + 4];
            mma16(acc[j], a[kc][0], a[kc][1], a[kc][2], a[kc][3], b0, b1);
        }
    }

    // bounce to smem (conflict-free)
    const int loc0 = 16*rw + g;
    #pragma unroll
    for (int j = 0; j < 12; j++) {
        int jj = jh + j;
        int m = jj >> 3;
        float sc = (jj < 8) ? SCALE_LOG2 : 1.0f;
        int wd = 4*(jj & 7) + t4;
        unsigned w0, w1;
        PACK2(w0, acc[j][1]*sc, acc[j][0]*sc);
        PACK2(w1, acc[j][3]*sc, acc[j][2]*sc);
        sout[m*64*OST + loc0*OST + wd]     = w0;
        sout[m*64*OST + (loc0+8)*OST + wd] = w1;
    }
    __syncthreads();

    // coalesced copy out: 3 x 64 rows x 8 uint4 = 1536 uint4
    const long gr0 = (long)blockIdx.x*64;
    #pragma unroll
    for (int i = 0; i < 6; i++) {
        int idx = tid + i*256;
        int m = idx >> 9, rem = idx & 511;
        int row = rem >> 3, wg = (rem & 7) << 2;
        uint4 v = *(uint4*)&sout[m*64*OST + row*OST + wg];
        unsigned* dst = (m == 0) ? g_Qh : (m == 1) ? g_Kh : g_Vh;
        *(uint4*)&dst[(gr0 + row)*32 + wg] = v;
    }
}

// ==== Kernel 2: flash attention — 256 thr / 128 q-rows / 2 CTAs per SM ====
#define PREFETCH(KS, BUF) do {                                                      \
    unsigned kd = smbase + (BUF)*SSBW*4;                                            \
    unsigned vd = kd + 128*KST3*4;                                                  \
    _Pragma("unroll")                                                               \
    for (int i_ = 0; i_ < 4; i_++) {                                                \
        int l_ = tid + i_*256;                                                      \
        int slot_ = l_ >> 3, wg_ = (l_ & 7) << 2;                                   \
        long soff_ = (long)((KS)*128 + slot_)*rsw + wg_;                            \
        CPA16(kd + (slot_*KST3 + wg_)*4, Kg + soff_);                               \
        CPA16(vd + (slot_*KST3 + wg_)*4, Vg + soff_);                               \
    }                                                                               \
    asm volatile("cp.async.commit_group;");                                         \
} while (0)

__global__ __launch_bounds__(256, 2) void attn_kernel() {
    extern __shared__ unsigned smu[];

    const int tid  = threadIdx.x;
    const int wid  = tid >> 5, lane = tid & 31;
    const int g    = lane >> 2, t4 = lane & 3;
    const int mq   = lane >> 3, rr = lane & 7;
    const int blk  = blockIdx.x;
    const int qb   = (NQB2 - 1) - blk / (B_*NW_);  // heaviest first (LPT)
    const int w    = blk % (B_*NW_);
    const int b    = w / NW_, wi = w % NW_;

    int base, r;
    if      (wi < 4) { base = wi*2048;     r = 1; }
    else if (wi < 6) { base = (wi-4)*4096; r = 2; }
    else             { base = 0;           r = 4; }

    const unsigned* Qg = g_Qh + ((long)b*N_ + base)*32;
    const unsigned* Kg = g_Kh + ((long)b*N_ + base)*32;
    const unsigned* Vg = g_Vh + ((long)b*N_ + base)*32;
    const int rsw = r * 32;

    const unsigned smbase = (unsigned)__cvta_generic_to_shared(smu);
    const unsigned kaddr0 = smbase + (((mq >> 1)*8 + rr)*KST3)*4 + (mq & 1)*16;
    const unsigned vaddr0 = smbase + 128*KST3*4 + (((mq & 1)*8 + rr)*KST3 + (mq >> 1)*4)*4;

    const int row0 = qb*128 + 16*wid;
    unsigned qa[4][4];
    {
        const unsigned* q0 = Qg + (long)(row0 + g)*rsw;
        const unsigned* q1 = q0 + (long)8*rsw;
        #pragma unroll
        for (int kc = 0; kc < 4; kc++) {
            qa[kc][0] = q0[8*kc + t4];
            qa[kc][1] = q1[8*kc + t4];
            qa[kc][2] = q0[8*kc + t4 + 4];
            qa[kc][3] = q1[8*kc + t4 + 4];
        }
    }

    float oacc[8][4];
    float m0 = -1e30f, m1 = -1e30f, l0v = 0.f, l1v = 0.f;
    #pragma unroll
    for (int j = 0; j < 8; j++)
        #pragma unroll
        for (int q = 0; q < 4; q++) oacc[j][q] = 0.f;

    const int nks = qb + 1;
    PREFETCH(0, 0);
    asm volatile("cp.async.wait_group 0;");
    __syncthreads();

    for (int ks = 0; ks < nks; ks++) {
        const int cur = ks & 1;
        const bool more = (ks + 1 < nks);
        if (more) PREFETCH(ks + 1, cur ^ 1);

        const unsigned kbuf = kaddr0 + cur*SSBW*4;
        const unsigned vbuf = vaddr0 + cur*SSBW*4;

        #pragma unroll
        for (int half = 0; half < 2; half++) {
            const int kbase = ks*128 + half*64;

            float sacc[8][4];
            #pragma unroll
            for (int j = 0; j < 8; j++)
                #pragma unroll
                for (int q = 0; q < 4; q++) sacc[j][q] = 0.f;

            #pragma unroll
            for (int kc = 0; kc < 4; kc++) {
                #pragma unroll
                for (int jp = 0; jp < 4; jp++) {
                    unsigned b00, b01, b10, b11;
                    unsigned addr = kbuf + (((half*64 + 16*jp)*KST3 + 8*kc) << 2);
                    LDSM4(b00, b01, b10, b11, addr);
                    mma16(sacc[2*jp  ], qa[kc][0], qa[kc][1], qa[kc][2], qa[kc][3], b00, b01);
                    mma16(sacc[2*jp+1], qa[kc][0], qa[kc][1], qa[kc][2], qa[kc][3], b10, b11);
                }
            }

            if (ks == qb) {
                int r0_ = row0 + g, r1_ = r0_ + 8;
                #pragma unroll
                for (int j = 0; j < 8; j++) {
                    int k0 = kbase + 8*j + 2*t4, k1 = k0 + 1;
                    if (k0 > r0_) sacc[j][0] = -1e30f;
                    if (k1 > r0_) sacc[j][1] = -1e30f;
                    if (k0 > r1_) sacc[j][2] = -1e30f;
                    if (k1 > r1_) sacc[j][3] = -1e30f;
                }
            }

            {
                float rm0 = -1e30f, rm1 = -1e30f;
                #pragma unroll
                for (int j = 0; j < 8; j++) {
                    rm0 = fmaxf(rm0, fmaxf(sacc[j][0], sacc[j][1]));
                    rm1 = fmaxf(rm1, fmaxf(sacc[j][2], sacc[j][3]));
                }
                rm0 = fmaxf(rm0, __shfl_xor_sync(0xffffffffu, rm0, 1));
                rm0 = fmaxf(rm0, __shfl_xor_sync(0xffffffffu, rm0, 2));
                rm1 = fmaxf(rm1, __shfl_xor_sync(0xffffffffu, rm1, 1));
                rm1 = fmaxf(rm1, __shfl_xor_sync(0xffffffffu, rm1, 2));
                float mn0 = fmaxf(m0, rm0), mn1 = fmaxf(m1, rm1);
                float c0 = ex2(m0 - mn0),   c1 = ex2(m1 - mn1);
                m0 = mn0; m1 = mn1;
                float rs0 = 0.f, rs1 = 0.f;
                #pragma unroll
                for (int j = 0; j < 8; j++) {
                    float p0 = ex2(sacc[j][0] - mn0); rs0 += p0; sacc[j][0] = p0;
                    float p1 = ex2(sacc[j][1] - mn0); rs0 += p1; sacc[j][1] = p1;
                    float p2 = ex2(sacc[j][2] - mn1); rs1 += p2; sacc[j][2] = p2;
                    float p3 = ex2(sacc[j][3] - mn1); rs1 += p3; sacc[j][3] = p3;
                }
                rs0 += __shfl_xor_sync(0xffffffffu, rs0, 1);
                rs0 += __shfl_xor_sync(0xffffffffu, rs0, 2);
                rs1 += __shfl_xor_sync(0xffffffffu, rs1, 1);
                rs1 += __shfl_xor_sync(0xffffffffu, rs1, 2);
                l0v = l0v*c0 + rs0;
                l1v = l1v*c1 + rs1;
                #pragma unroll
                for (int jv = 0; jv < 8; jv++) {
                    oacc[jv][0] *= c0; oacc[jv][1] *= c0;
                    oacc[jv][2] *= c1; oacc[jv][3] *= c1;
                }
            }

            #pragma unroll
            for (int u = 0; u < 4; u++) {
                unsigned a0, a1, a2, a3;
                PACK2(a0, sacc[2*u  ][1], sacc[2*u  ][0]);
                PACK2(a1, sacc[2*u  ][3], sacc[2*u  ][2]);
                PACK2(a2, sacc[2*u+1][1], sacc[2*u+1][0]);
                PACK2(a3, sacc[2*u+1][3], sacc[2*u+1][2]);
                const int kb = half*64 + 16*u;
                #pragma unroll
                for (int jvp = 0; jvp < 4; jvp++) {
                    unsigned r0v, r1v, r2v, r3v;
                    unsigned addr = vbuf + ((kb*KST3 + 8*jvp) << 2);
                    LDSM4T(r0v, r1v, r2v, r3v, addr);
                    mma16(oacc[2*jvp  ], a0, a1, a2, a3, r0v, r1v);
                    mma16(oacc[2*jvp+1], a0, a1, a2, a3, r2v, r3v);
                }
            }
        }

        if (more) asm volatile("cp.async.wait_group 0;");
        __syncthreads();
    }

    // ---- epilogue: packed fp16 O + denominator ----
    unsigned* Og = g_Oh + (long)(b*NW_ + wi)*M_*32;
    float* Dg = g_D + (long)(b*NW_ + wi)*M_;
    {
        int r0_ = row0 + g, r1_ = r0_ + 8;
        float i0 = 1.0f / l0v, i1 = 1.0f / l1v;
        #pragma unroll
        for (int jv = 0; jv < 8; jv++) {
            unsigned p0, p1;
            PACK2(p0, oacc[jv][1]*i0, oacc[jv][0]*i0);
            PACK2(p1, oacc[jv][3]*i1, oacc[jv][2]*i1);
            Og[(long)r0_*32 + 4*jv + t4] = p0;
            Og[(long)r1_*32 + 4*jv + t4] = p1;
        }
        if (t4 == 0) {
            Dg[r0_] = l0v * ex2(m0);
            Dg[r1_] = l1v * ex2(m1);
        }
    }
}

// ============ Kernel 3: mix — fp16 packed reads, float2 coalesced writes ============
__global__ __launch_bounds__(256) void mix_kernel(float* __restrict__ out) {
    const int tid = threadIdx.x;
    const int c2 = tid & 31;
    const int gp = blockIdx.x*8 + (tid >> 5);
    const int b = gp >> 13;
    const int p = gp & (N_-1);

    float nx = 0.f, ny = 0.f, dsum = 0.f;
    #define ACC1(SLOT, ROW) do {                                        \
        long i_ = ((long)b*NW_ + (SLOT))*M_ + (ROW);                    \
        float d_ = g_D[i_];                                             \
        unsigned w_ = g_Oh[i_*32 + c2];                                 \
        float2 f_ = __half22float2(*reinterpret_cast<__half2*>(&w_));   \
        dsum += d_;                                                     \
        nx += d_ * f_.x;                                                \
        ny += d_ * f_.y;                                                \
    } while (0)

    int w0 = p >> 11, r0 = p & 2047;
    ACC1(w0, r0);
    if ((p & 1) == 0) {
        int w1 = 4 + (p >> 12), r1 = (p & 4095) >> 1;
        ACC1(w1, r1);
    }
    if ((p & 3) == 0) {
        ACC1(6, p >> 2);
    }
    #undef ACC1
    float inv = 1.0f / dsum;
    *(float2*)&out[((long)b*N_ + p)*C_ + 2*c2] = make_float2(nx*inv, ny*inv);
}

// =======================================================================
extern "C" void kernel_launch(void* const* d_in, const int* in_sizes, int n_in,
                              void* d_out, int out_size) {
    (void)in_sizes; (void)n_in; (void)out_size;
    const float* x  = (const float*)d_in[0];
    const float* Wq = (const float*)d_in[1];
    const float* Wk = (const float*)d_in[2];
    const float* Wv = (const float*)d_in[3];
    float* out = (float*)d_out;

    const int smem1 = (192*WST2 + 3*64*OST) * 4;    // 55296 B
    const int smem2 = 2*SSBW*4;                     // 73728 B
    cudaFuncSetAttribute(qkv_kernel,  cudaFuncAttributeMaxDynamicSharedMemorySize, smem1);
    cudaFuncSetAttribute(attn_kernel, cudaFuncAttributeMaxDynamicSharedMemorySize, smem2);

    qkv_kernel<<<(B_*N_)/64, 256, smem1>>>(x, Wq, Wk, Wv);
    attn_kernel<<<NQB2 * B_ * NW_, 256, smem2>>>();
    mix_kernel<<<(B_*N_)/8, 256>>>(out);
}